// round 10
// baseline (speedup 1.0000x reference)
#include <cuda_runtime.h>
#include <cuda_fp16.h>
#include <cstdint>

#define BB 8
#define CC 128
#define MM 16
#define HW 16384            // H*W
#define PP 64               // spatial positions per tile
#define TT 4                // tiles per block
#define CHUNKS_PER_B 64     // HW / (PP*TT)
#define NBLK (BB * CHUNKS_PER_B)   // 512 main blocks

// Ordered-uint max accumulator per (b, m-1, c); re-initialized every launch.
__device__ unsigned g_accum[BB * 15 * CC];

// Monotone float <-> unsigned order-preserving encoding.
__device__ __forceinline__ unsigned ford(float f) {
    unsigned u = __float_as_uint(f);
    return (u & 0x80000000u) ? ~u : (u | 0x80000000u);
}
__device__ __forceinline__ float fdec(unsigned s) {
    unsigned u = (s & 0x80000000u) ? (s & 0x7FFFFFFFu) : ~s;
    return __uint_as_float(u);
}

// ---- Init: g_accum = ford(-inf) = 0x007FFFFF ----
__global__ __launch_bounds__(1024)
void vfm_init() {
    g_accum[blockIdx.x * 1024 + threadIdx.x] = 0x007FFFFFu;   // grid 15
}

// ---- Main: block = (b, 256-position chunk), 256 threads ----
// Warps span channels; mask bits warp-uniform per position. 8 half2 accs.
// Register-prefetch pipeline: next tile's LDGs issued before compute(t).
__global__ __launch_bounds__(256)
void vfm_main(const float* __restrict__ enc, const int* __restrict__ masks) {
    __shared__ __half tile_h[CC][PP + 2];            // stride 66 halves: conflict-free
    __shared__ __align__(16) __half2 negs2[PP][8];   // one 16B row per position
    __shared__ float comb[4][32][15];                // cross-half combine

    const int bx    = blockIdx.x;
    const int b     = bx / CHUNKS_PER_B;
    const int chunk = bx % CHUNKS_PER_B;
    const int p0    = chunk * (PP * TT);

    const int tid  = threadIdx.x;
    const int w    = tid >> 5;
    const int lane = tid & 31;
    const int cg   = w & 3;
    const int half = w >> 2;
    const int c    = cg * 32 + lane;

    __half2 acc2[8];
    {
        unsigned ninf2 = 0xFC00FC00u;
        __half2 hn = *reinterpret_cast<__half2*>(&ninf2);
#pragma unroll
        for (int j = 0; j < 8; j++) acc2[j] = hn;
    }

    const float* encb  = enc   + (size_t)b * CC * HW;
    const int*   maskb = masks + (size_t)b * MM * HW;

    // Per-thread staging coordinates (fixed across tiles)
    const int s_cr = tid >> 5;             // used with +32*i rows? no: u-based below
    (void)s_cr;
    const int mp_p  = tid & 63;
    const int mg    = tid >> 6;            // 0..3
    const int m0    = 4 * mg + 1;

    float2 f2r[16];
    int    mkr[4];

    // ---- prefetch(t=0) ----
    {
        const int pb = p0;
#pragma unroll
        for (int i = 0; i < 16; i++) {
            int u  = tid + i * 256;
            int cr = u >> 5, ph = u & 31;
            f2r[i] = *reinterpret_cast<const float2*>(&encb[(size_t)cr * HW + pb + ph * 2]);
        }
        const int* mp = maskb + pb + mp_p;
#pragma unroll
        for (int k = 0; k < 4; k++)
            mkr[k] = (m0 + k < MM) ? mp[(size_t)(m0 + k) * HW] : 1;
    }

    for (int t = 0; t < TT; t++) {
        // ---- store phase: regs -> SMEM ----
#pragma unroll
        for (int i = 0; i < 16; i++) {
            int u  = tid + i * 256;
            int cr = u >> 5, ph = u & 31;
            *reinterpret_cast<__half2*>(&tile_h[cr][ph * 2]) =
                __floats2half2_rn(f2r[i].x, f2r[i].y);
        }
        {
            unsigned lo0 = mkr[0] ? 0u : 0xFC00u;
            unsigned hi0 = mkr[1] ? 0u : 0xFC00u;
            unsigned lo1 = mkr[2] ? 0u : 0xFC00u;
            unsigned hi1 = mkr[3] ? 0u : 0xFC00u;
            *reinterpret_cast<uint2*>(&negs2[mp_p][mg * 2]) =
                make_uint2(lo0 | (hi0 << 16), lo1 | (hi1 << 16));
        }
        __syncthreads();

        // ---- prefetch(t+1): LDGs hidden under compute(t) ----
        if (t + 1 < TT) {
            const int pb = p0 + (t + 1) * PP;
#pragma unroll
            for (int i = 0; i < 16; i++) {
                int u  = tid + i * 256;
                int cr = u >> 5, ph = u & 31;
                f2r[i] = *reinterpret_cast<const float2*>(&encb[(size_t)cr * HW + pb + ph * 2]);
            }
            const int* mp = maskb + pb + mp_p;
#pragma unroll
            for (int k = 0; k < 4; k++)
                mkr[k] = (m0 + k < MM) ? mp[(size_t)(m0 + k) * HW] : 1;
        }

        // ---- compute(t): 8 HADD2 + 8 HMAX2 per position ----
        const int ps = half * 32;
#pragma unroll 4
        for (int p = ps; p < ps + 32; p++) {
            __half2 v2 = __half2half2(tile_h[c][p]);
            uint4 nu = *reinterpret_cast<const uint4*>(&negs2[p][0]);
            __half2 n0 = *reinterpret_cast<__half2*>(&nu.x);
            __half2 n1 = *reinterpret_cast<__half2*>(&nu.y);
            __half2 n2 = *reinterpret_cast<__half2*>(&nu.z);
            __half2 n3 = *reinterpret_cast<__half2*>(&nu.w);
            acc2[0] = __hmax2(acc2[0], __hadd2(v2, n0));
            acc2[1] = __hmax2(acc2[1], __hadd2(v2, n1));
            acc2[2] = __hmax2(acc2[2], __hadd2(v2, n2));
            acc2[3] = __hmax2(acc2[3], __hadd2(v2, n3));
            uint4 nv = *reinterpret_cast<const uint4*>(&negs2[p][4]);
            __half2 n4 = *reinterpret_cast<__half2*>(&nv.x);
            __half2 n5 = *reinterpret_cast<__half2*>(&nv.y);
            __half2 n6 = *reinterpret_cast<__half2*>(&nv.z);
            __half2 n7 = *reinterpret_cast<__half2*>(&nv.w);
            acc2[4] = __hmax2(acc2[4], __hadd2(v2, n4));
            acc2[5] = __hmax2(acc2[5], __hadd2(v2, n5));
            acc2[6] = __hmax2(acc2[6], __hadd2(v2, n6));
            acc2[7] = __hmax2(acc2[7], __hadd2(v2, n7));
        }
        __syncthreads();   // all readers done before next store phase
    }

    // ---- Unpack, combine halves, atomic-max into g_accum ----
    float acc[15];
#pragma unroll
    for (int j = 0; j < 8; j++) {
        acc[2 * j] = __low2float(acc2[j]);
        if (2 * j + 1 < 15) acc[2 * j + 1] = __high2float(acc2[j]);
    }

    if (half == 1) {
#pragma unroll
        for (int m = 0; m < 15; m++) comb[cg][lane][m] = acc[m];
    }
    __syncthreads();
    if (half == 0) {
        unsigned* ap = g_accum + (size_t)(b * 15) * CC + c;
#pragma unroll
        for (int m = 0; m < 15; m++) {
            float vmx = fmaxf(acc[m], comb[cg][lane][m]);
            atomicMax(&ap[(size_t)m * CC], ford(vmx));   // REDG.MAX, fire-and-forget
        }
    }
}

// ---- Decode: g_accum -> out [B, C, 15, 1] ----
__global__ __launch_bounds__(128)
void vfm_final(float* __restrict__ out) {
    const int b = blockIdx.x / 15;
    const int m = blockIdx.x % 15;
    const int c = threadIdx.x;
    unsigned s = g_accum[(size_t)(b * 15 + m) * CC + c];   // coalesced read
    out[((size_t)(b * CC + c)) * 15 + m] = fdec(s);
}

extern "C" void kernel_launch(void* const* d_in, const int* in_sizes, int n_in,
                              void* d_out, int out_size) {
    const float* enc   = (const float*)d_in[0];   // [8,128,128,128] f32
    const int*   masks = (const int*)d_in[1];     // [8,16,128,128] int32
    float* out = (float*)d_out;                   // [8,128,15,1] f32

    vfm_init<<<15, 1024>>>();
    vfm_main<<<NBLK, 256>>>(enc, masks);
    vfm_final<<<120, 128>>>(out);
}